// round 8
// baseline (speedup 1.0000x reference)
#include <cuda_runtime.h>
#include <cuda_fp16.h>
#include <math.h>

#define NNODES 50000
#define NEDGES 800000
#define FEAT   120

// Scratch (static __device__ arrays — allocation-free per harness rules)
__device__ __half2 g_qWh[(size_t)NNODES * FEAT * 2]; // [n][f][4 heads as 2x half2], 48 MB
__device__ __half  g_kh [(size_t)NNODES * FEAT];     // 12 MB
__device__ float   g_v  [(size_t)NNODES * FEAT];     // 24 MB
__device__ float   g_z  [NNODES];
// dst-sorted edge list
__device__ int g_cnt [NNODES];
__device__ int g_cur [NNODES];
__device__ int g_off [NNODES + 1];
__device__ int g_ssrc[NEDGES];
__device__ int g_sdst[NEDGES];

__device__ __forceinline__ void store_qw(int n, int f, float4 a, float c) {
    __half2 h01 = __floats2half2_rn(a.x * c, a.y * c);
    __half2 h23 = __floats2half2_rn(a.z * c, a.w * c);
    uint2 u;
    u.x = *reinterpret_cast<unsigned*>(&h01);
    u.y = *reinterpret_cast<unsigned*>(&h23);
    reinterpret_cast<uint2*>(g_qWh)[(size_t)n * FEAT + f] = u;
}

// ---------------------------------------------------------------------------
// Node kernel (exact R4 structure): one warp per 2 nodes, 8 warps per block.
// 50000 = 16 * 3125 exactly -> no bounds checks.
// ---------------------------------------------------------------------------
__global__ __launch_bounds__(256) void node_kernel(
    const float* __restrict__ x,
    const float* __restrict__ Wq0, const float* __restrict__ Wq1, const float* __restrict__ Wq2,
    const float* __restrict__ Wk0, const float* __restrict__ Wk1, const float* __restrict__ Wk2,
    const float* __restrict__ Wv0, const float* __restrict__ Wv1, const float* __restrict__ Wv2,
    const float* __restrict__ Wd0, const float* __restrict__ Wd1, const float* __restrict__ Wd2,
    float* __restrict__ out)
{
    __shared__ float sX[8][2][FEAT];
    __shared__ float sQ[8][2][FEAT];

    const int warp = threadIdx.x >> 5;
    const int lane = threadIdx.x & 31;
    const int n0 = blockIdx.x * 16 + warp * 2;
    const int n1 = n0 + 1;

    float* xs0 = sX[warp][0];
    float* xs1 = sX[warp][1];
    float* qs0 = sQ[warp][0];
    float* qs1 = sQ[warp][1];

    for (int f = lane; f < FEAT; f += 32) {
        xs0[f] = x[(size_t)n0 * FEAT + f];
        xs1[f] = x[(size_t)n1 * FEAT + f];
        out[(size_t)n0 * FEAT + f] = 0.0f;   // out accumulates edge sums
        out[(size_t)n1 * FEAT + f] = 0.0f;
    }
    if (lane == 0) { g_z[n0] = 0.0f; g_z[n1] = 0.0f; }
    __syncwarp();

    const float inv_s32 = 0.1767766953f;   // 1/sqrt(32)
    const float inv_s16 = 0.25f;
    const float inv_s8  = 0.3535533906f;   // 1/sqrt(8)

    __half* kp0 = g_kh + (size_t)n0 * FEAT;
    __half* kp1 = g_kh + (size_t)n1 * FEAT;
    float*  vp0 = g_v  + (size_t)n0 * FEAT;
    float*  vp1 = g_v  + (size_t)n1 * FEAT;

    #pragma unroll 1
    for (int pass = 0; pass < 3; ++pass) {
        const float* W0 = (pass == 0) ? Wq0 : ((pass == 1) ? Wk0 : Wv0);
        const float* W1 = (pass == 0) ? Wq1 : ((pass == 1) ? Wk1 : Wv1);
        const float* W2 = (pass == 0) ? Wq2 : ((pass == 1) ? Wk2 : Wv2);

        // l=0: output j = lane
        {
            float a0 = 0.f, a1 = 0.f;
            #pragma unroll
            for (int i = 0; i < 32; ++i) {
                float w = __ldg(&W0[i * 32 + lane]);
                a0 += xs0[i] * w;
                a1 += xs1[i] * w;
            }
            a0 *= inv_s32; a1 *= inv_s32;
            float nn0 = sqrtf(a0*a0 + 1e-10f), nn1 = sqrtf(a1*a1 + 1e-10f);
            float y0 = (1.0f / (1.0f + __expf(-nn0))) / nn0 * a0;
            float y1 = (1.0f / (1.0f + __expf(-nn1))) / nn1 * a1;
            if (pass == 0)      { qs0[lane] = y0; qs1[lane] = y1; }
            else if (pass == 1) { kp0[lane] = __float2half_rn(y0); kp1[lane] = __float2half_rn(y1); }
            else                { vp0[lane] = y0; vp1[lane] = y1; }
        }
        // l=1: lanes 0..15, output j = lane
        if (lane < 16) {
            float r0[3], r1[3];
            #pragma unroll
            for (int m = 0; m < 3; ++m) { r0[m] = 0.f; r1[m] = 0.f; }
            #pragma unroll
            for (int i = 0; i < 16; ++i) {
                float w = __ldg(&W1[i * 16 + lane]);
                #pragma unroll
                for (int m = 0; m < 3; ++m) {
                    r0[m] += xs0[32 + i*3 + m] * w;
                    r1[m] += xs1[32 + i*3 + m] * w;
                }
            }
            float ss0 = 0.f, ss1 = 0.f;
            #pragma unroll
            for (int m = 0; m < 3; ++m) {
                r0[m] *= inv_s16; r1[m] *= inv_s16;
                ss0 += r0[m]*r0[m]; ss1 += r1[m]*r1[m];
            }
            float nn0 = sqrtf(ss0 + 1e-10f), nn1 = sqrtf(ss1 + 1e-10f);
            float sc0 = (1.0f / (1.0f + __expf(-nn0))) / nn0;
            float sc1 = (1.0f / (1.0f + __expf(-nn1))) / nn1;
            #pragma unroll
            for (int m = 0; m < 3; ++m) {
                int f = 32 + lane*3 + m;
                float y0 = sc0 * r0[m], y1 = sc1 * r1[m];
                if (pass == 0)      { qs0[f] = y0; qs1[f] = y1; }
                else if (pass == 1) { kp0[f] = __float2half_rn(y0); kp1[f] = __float2half_rn(y1); }
                else                { vp0[f] = y0; vp1[f] = y1; }
            }
        }
        // l=2: lanes 16..23, output j = lane-16
        else if (lane < 24) {
            const int j = lane - 16;
            float r0[5], r1[5];
            #pragma unroll
            for (int m = 0; m < 5; ++m) { r0[m] = 0.f; r1[m] = 0.f; }
            #pragma unroll
            for (int i = 0; i < 8; ++i) {
                float w = __ldg(&W2[i * 8 + j]);
                #pragma unroll
                for (int m = 0; m < 5; ++m) {
                    r0[m] += xs0[80 + i*5 + m] * w;
                    r1[m] += xs1[80 + i*5 + m] * w;
                }
            }
            float ss0 = 0.f, ss1 = 0.f;
            #pragma unroll
            for (int m = 0; m < 5; ++m) {
                r0[m] *= inv_s8; r1[m] *= inv_s8;
                ss0 += r0[m]*r0[m]; ss1 += r1[m]*r1[m];
            }
            float nn0 = sqrtf(ss0 + 1e-10f), nn1 = sqrtf(ss1 + 1e-10f);
            float sc0 = (1.0f / (1.0f + __expf(-nn0))) / nn0;
            float sc1 = (1.0f / (1.0f + __expf(-nn1))) / nn1;
            #pragma unroll
            for (int m = 0; m < 5; ++m) {
                int f = 80 + j*5 + m;
                float y0 = sc0 * r0[m], y1 = sc1 * r1[m];
                if (pass == 0)      { qs0[f] = y0; qs1[f] = y1; }
                else if (pass == 1) { kp0[f] = __float2half_rn(y0); kp1[f] = __float2half_rn(y1); }
                else                { vp0[f] = y0; vp1[f] = y1; }
            }
        }
        __syncwarp();
    }

    // ---- Wd contraction: qW[n][f][4], both nodes share every Wd wavefront ----
    const float c0 = 0.02176061898f;     // 1/sqrt(2112)
    const float c1 = c0 * 0.5773502692f; // c0/sqrt(3)
    const float c2 = c0 * 0.4472135955f; // c0/sqrt(5)
    const float4* D0 = reinterpret_cast<const float4*>(Wd0);
    const float4* D1 = reinterpret_cast<const float4*>(Wd1);
    const float4* D2 = reinterpret_cast<const float4*>(Wd2);

    // l=0: j = lane
    {
        float4 A0 = make_float4(0.f,0.f,0.f,0.f);
        float4 A1 = make_float4(0.f,0.f,0.f,0.f);
        #pragma unroll
        for (int i = 0; i < 32; ++i) {
            float4 w = __ldg(&D0[i * 32 + lane]);
            float q0 = qs0[i], q1 = qs1[i];
            A0.x += q0*w.x; A0.y += q0*w.y; A0.z += q0*w.z; A0.w += q0*w.w;
            A1.x += q1*w.x; A1.y += q1*w.y; A1.z += q1*w.z; A1.w += q1*w.w;
        }
        store_qw(n0, lane, A0, c0);
        store_qw(n1, lane, A1, c0);
    }
    // l=1: lanes 0..15, j = lane
    if (lane < 16) {
        float4 B0[3], B1[3];
        #pragma unroll
        for (int m = 0; m < 3; ++m) {
            B0[m] = make_float4(0.f,0.f,0.f,0.f);
            B1[m] = make_float4(0.f,0.f,0.f,0.f);
        }
        #pragma unroll
        for (int i = 0; i < 16; ++i) {
            float4 w = __ldg(&D1[i * 16 + lane]);
            #pragma unroll
            for (int m = 0; m < 3; ++m) {
                float q0 = qs0[32 + i*3 + m], q1 = qs1[32 + i*3 + m];
                B0[m].x += q0*w.x; B0[m].y += q0*w.y; B0[m].z += q0*w.z; B0[m].w += q0*w.w;
                B1[m].x += q1*w.x; B1[m].y += q1*w.y; B1[m].z += q1*w.z; B1[m].w += q1*w.w;
            }
        }
        #pragma unroll
        for (int m = 0; m < 3; ++m) {
            int f = 32 + lane*3 + m;
            store_qw(n0, f, B0[m], c1);
            store_qw(n1, f, B1[m], c1);
        }
    }
    // l=2: lanes 16..23, j = lane-16
    else if (lane < 24) {
        const int j = lane - 16;
        float4 C0[5], C1[5];
        #pragma unroll
        for (int m = 0; m < 5; ++m) {
            C0[m] = make_float4(0.f,0.f,0.f,0.f);
            C1[m] = make_float4(0.f,0.f,0.f,0.f);
        }
        #pragma unroll
        for (int i = 0; i < 8; ++i) {
            float4 w = __ldg(&D2[i * 8 + j]);
            #pragma unroll
            for (int m = 0; m < 5; ++m) {
                float q0 = qs0[80 + i*5 + m], q1 = qs1[80 + i*5 + m];
                C0[m].x += q0*w.x; C0[m].y += q0*w.y; C0[m].z += q0*w.z; C0[m].w += q0*w.w;
                C1[m].x += q1*w.x; C1[m].y += q1*w.y; C1[m].z += q1*w.z; C1[m].w += q1*w.w;
            }
        }
        #pragma unroll
        for (int m = 0; m < 5; ++m) {
            int f = 80 + j*5 + m;
            store_qw(n0, f, C0[m], c2);
            store_qw(n1, f, C1[m], c2);
        }
    }
}

// ---------------------------------------------------------------------------
// Binning kernels (dst-sorted edge list)
// ---------------------------------------------------------------------------
__global__ void zero_cnt_kernel() {
    int i = blockIdx.x * blockDim.x + threadIdx.x;
    if (i < NNODES) g_cnt[i] = 0;
}

__global__ void hist_kernel(const int* __restrict__ dsts) {
    int e = blockIdx.x * blockDim.x + threadIdx.x;
    if (e < NEDGES) atomicAdd(&g_cnt[dsts[e]], 1);
}

// Single-block exclusive scan over g_cnt -> g_off, g_cur. 1024 threads.
__global__ __launch_bounds__(1024) void scan_kernel() {
    __shared__ int sp[1024];
    const int t = threadIdx.x;
    const int CH = (NNODES + 1023) / 1024;          // 49
    const int beg = t * CH;
    const int end = (beg + CH < NNODES) ? beg + CH : NNODES;

    int sum = 0;
    for (int i = beg; i < end; ++i) sum += g_cnt[i];
    sp[t] = sum;
    __syncthreads();
    for (int d = 1; d < 1024; d <<= 1) {
        int v = (t >= d) ? sp[t - d] : 0;
        __syncthreads();
        sp[t] += v;
        __syncthreads();
    }
    int run = (t > 0) ? sp[t - 1] : 0;
    for (int i = beg; i < end; ++i) {
        g_off[i] = run;
        g_cur[i] = run;
        run += g_cnt[i];
    }
    if (end == NNODES && beg < NNODES) g_off[NNODES] = run;
}

__global__ void scatter_kernel(const int* __restrict__ dsts, const int* __restrict__ srcs) {
    int e = blockIdx.x * blockDim.x + threadIdx.x;
    if (e < NEDGES) {
        int d = dsts[e];
        int p = atomicAdd(&g_cur[d], 1);
        g_ssrc[p] = srcs[e];
        g_sdst[p] = d;
    }
}

// ---------------------------------------------------------------------------
// Fused edge kernel over the SORTED edge list: one warp per edge.
// Consecutive warps share dst -> qW row served from L1 after first touch.
// ev = mean_h exp(qW[dst]·k[src]); z[dst] += ev; out[dst] += sqrt(ev)*v[src].
// ---------------------------------------------------------------------------
__global__ __launch_bounds__(256) void edge_kernel(float* __restrict__ out)
{
    const int e = (blockIdx.x * blockDim.x + threadIdx.x) >> 5;
    const int lane = threadIdx.x & 31;
    if (e >= NEDGES) return;
    const int d = g_sdst[e];
    const int s = g_ssrc[e];

    const uint4*   qw4 = reinterpret_cast<const uint4*>(g_qWh + (size_t)d * FEAT * 2); // 60 entries
    const __half2* kr  = reinterpret_cast<const __half2*>(g_kh + (size_t)s * FEAT);    // 60 entries

    float ax = 0.f, ay = 0.f, az = 0.f, aw = 0.f;
    {
        uint4 q = qw4[lane];
        float2 kf = __half22float2(kr[lane]);
        float2 e0h01 = __half22float2(*reinterpret_cast<__half2*>(&q.x));
        float2 e0h23 = __half22float2(*reinterpret_cast<__half2*>(&q.y));
        float2 e1h01 = __half22float2(*reinterpret_cast<__half2*>(&q.z));
        float2 e1h23 = __half22float2(*reinterpret_cast<__half2*>(&q.w));
        ax += kf.x*e0h01.x + kf.y*e1h01.x; ay += kf.x*e0h01.y + kf.y*e1h01.y;
        az += kf.x*e0h23.x + kf.y*e1h23.x; aw += kf.x*e0h23.y + kf.y*e1h23.y;
    }
    if (lane < 28) {
        uint4 q = qw4[32 + lane];
        float2 kf = __half22float2(kr[32 + lane]);
        float2 e0h01 = __half22float2(*reinterpret_cast<__half2*>(&q.x));
        float2 e0h23 = __half22float2(*reinterpret_cast<__half2*>(&q.y));
        float2 e1h01 = __half22float2(*reinterpret_cast<__half2*>(&q.z));
        float2 e1h23 = __half22float2(*reinterpret_cast<__half2*>(&q.w));
        ax += kf.x*e0h01.x + kf.y*e1h01.x; ay += kf.x*e0h01.y + kf.y*e1h01.y;
        az += kf.x*e0h23.x + kf.y*e1h23.x; aw += kf.x*e0h23.y + kf.y*e1h23.y;
    }
    #pragma unroll
    for (int off = 16; off > 0; off >>= 1) {
        ax += __shfl_xor_sync(0xffffffffu, ax, off);
        ay += __shfl_xor_sync(0xffffffffu, ay, off);
        az += __shfl_xor_sync(0xffffffffu, az, off);
        aw += __shfl_xor_sync(0xffffffffu, aw, off);
    }
    const float ev = 0.25f * (__expf(ax) + __expf(ay) + __expf(az) + __expf(aw));
    if (lane == 0) atomicAdd(&g_z[d], ev);

    const float w = sqrtf(ev);
    if (lane < FEAT / 4) {  // 30 lanes, float4 chunk f = 4*lane
        float4 v4 = reinterpret_cast<const float4*>(g_v + (size_t)s * FEAT)[lane];
        float* p = out + (size_t)d * FEAT + lane * 4;
        asm volatile("red.global.add.v4.f32 [%0], {%1, %2, %3, %4};"
                     :: "l"(p), "f"(w * v4.x), "f"(w * v4.y), "f"(w * v4.z), "f"(w * v4.w)
                     : "memory");
    }
}

// ---------------------------------------------------------------------------
// Finalize: out = v_node + out * rsqrt(z)   (z==0 -> no edges -> out sum is 0)
// ---------------------------------------------------------------------------
__global__ __launch_bounds__(256) void finalize_kernel(float* __restrict__ out)
{
    const int t = blockIdx.x * blockDim.x + threadIdx.x;
    if (t >= NNODES * (FEAT / 4)) return;
    const int n = t / (FEAT / 4);
    const float zz = g_z[n];
    const float sc = (zz > 0.0f) ? rsqrtf(zz) : 0.0f;
    float4 o = reinterpret_cast<float4*>(out)[t];
    float4 v = reinterpret_cast<const float4*>(g_v)[t];
    o.x = v.x + o.x * sc;
    o.y = v.y + o.y * sc;
    o.z = v.z + o.z * sc;
    o.w = v.w + o.w * sc;
    reinterpret_cast<float4*>(out)[t] = o;
}

// ---------------------------------------------------------------------------
extern "C" void kernel_launch(void* const* d_in, const int* in_sizes, int n_in,
                              void* d_out, int out_size)
{
    const float* x   = (const float*)d_in[0];
    const float* Wq0 = (const float*)d_in[1];
    const float* Wq1 = (const float*)d_in[2];
    const float* Wq2 = (const float*)d_in[3];
    const float* Wk0 = (const float*)d_in[4];
    const float* Wk1 = (const float*)d_in[5];
    const float* Wk2 = (const float*)d_in[6];
    const float* Wv0 = (const float*)d_in[7];
    const float* Wv1 = (const float*)d_in[8];
    const float* Wv2 = (const float*)d_in[9];
    const float* Wd0 = (const float*)d_in[10];
    const float* Wd1 = (const float*)d_in[11];
    const float* Wd2 = (const float*)d_in[12];
    const int* edge_dst = (const int*)d_in[13];
    const int* edge_src = (const int*)d_in[14];
    float* out = (float*)d_out;

    // Binning (dst-sorted edge list)
    zero_cnt_kernel<<<(NNODES + 255) / 256, 256>>>();
    hist_kernel<<<(NEDGES + 255) / 256, 256>>>(edge_dst);
    scan_kernel<<<1, 1024>>>();
    scatter_kernel<<<(NEDGES + 255) / 256, 256>>>(edge_dst, edge_src);

    // Node kernel: 16 nodes/block (2 per warp), 50000/16 = 3125 blocks
    node_kernel<<<NNODES / 16, 256>>>(x, Wq0, Wq1, Wq2, Wk0, Wk1, Wk2,
                                      Wv0, Wv1, Wv2, Wd0, Wd1, Wd2, out);

    // Fused edge kernel over sorted edges: 8 edges/block (one warp each)
    edge_kernel<<<(NEDGES + 7) / 8, 256>>>(out);

    // Finalize: one thread per float4 of out
    const int nt = NNODES * (FEAT / 4);
    finalize_kernel<<<(nt + 255) / 256, 256>>>(out);
}

// round 9
// speedup vs baseline: 1.0775x; 1.0775x over previous
#include <cuda_runtime.h>
#include <cuda_fp16.h>
#include <math.h>

#define NNODES 50000
#define NEDGES 800000
#define FEAT   120

// Scratch (static __device__ arrays — allocation-free per harness rules)
__device__ __half2 g_qWh[(size_t)NNODES * FEAT * 2]; // [n][f][4 heads as 2x half2], 48 MB
__device__ __half  g_kh [(size_t)NNODES * FEAT];     // 12 MB
__device__ float   g_v  [(size_t)NNODES * FEAT];     // 24 MB
// CSR (dst-sorted src list)
__device__ int g_cnt [NNODES];
__device__ int g_cur [NNODES];
__device__ int g_off [NNODES + 1];
__device__ int g_ssrc[NEDGES];

__device__ __forceinline__ void store_qw(int n, int f, float4 a, float c) {
    __half2 h01 = __floats2half2_rn(a.x * c, a.y * c);
    __half2 h23 = __floats2half2_rn(a.z * c, a.w * c);
    uint2 u;
    u.x = *reinterpret_cast<unsigned*>(&h01);
    u.y = *reinterpret_cast<unsigned*>(&h23);
    reinterpret_cast<uint2*>(g_qWh)[(size_t)n * FEAT + f] = u;
}

// ---------------------------------------------------------------------------
// Node kernel (R4 structure): one warp per 2 nodes, 8 warps per block.
// 50000 = 16 * 3125 exactly -> no bounds checks.
// ---------------------------------------------------------------------------
__global__ __launch_bounds__(256) void node_kernel(
    const float* __restrict__ x,
    const float* __restrict__ Wq0, const float* __restrict__ Wq1, const float* __restrict__ Wq2,
    const float* __restrict__ Wk0, const float* __restrict__ Wk1, const float* __restrict__ Wk2,
    const float* __restrict__ Wv0, const float* __restrict__ Wv1, const float* __restrict__ Wv2,
    const float* __restrict__ Wd0, const float* __restrict__ Wd1, const float* __restrict__ Wd2)
{
    __shared__ float sX[8][2][FEAT];
    __shared__ float sQ[8][2][FEAT];

    const int warp = threadIdx.x >> 5;
    const int lane = threadIdx.x & 31;
    const int n0 = blockIdx.x * 16 + warp * 2;
    const int n1 = n0 + 1;

    float* xs0 = sX[warp][0];
    float* xs1 = sX[warp][1];
    float* qs0 = sQ[warp][0];
    float* qs1 = sQ[warp][1];

    for (int f = lane; f < FEAT; f += 32) {
        xs0[f] = x[(size_t)n0 * FEAT + f];
        xs1[f] = x[(size_t)n1 * FEAT + f];
    }
    __syncwarp();

    const float inv_s32 = 0.1767766953f;   // 1/sqrt(32)
    const float inv_s16 = 0.25f;
    const float inv_s8  = 0.3535533906f;   // 1/sqrt(8)

    __half* kp0 = g_kh + (size_t)n0 * FEAT;
    __half* kp1 = g_kh + (size_t)n1 * FEAT;
    float*  vp0 = g_v  + (size_t)n0 * FEAT;
    float*  vp1 = g_v  + (size_t)n1 * FEAT;

    #pragma unroll 1
    for (int pass = 0; pass < 3; ++pass) {
        const float* W0 = (pass == 0) ? Wq0 : ((pass == 1) ? Wk0 : Wv0);
        const float* W1 = (pass == 0) ? Wq1 : ((pass == 1) ? Wk1 : Wv1);
        const float* W2 = (pass == 0) ? Wq2 : ((pass == 1) ? Wk2 : Wv2);

        // l=0: output j = lane
        {
            float a0 = 0.f, a1 = 0.f;
            #pragma unroll
            for (int i = 0; i < 32; ++i) {
                float w = __ldg(&W0[i * 32 + lane]);
                a0 += xs0[i] * w;
                a1 += xs1[i] * w;
            }
            a0 *= inv_s32; a1 *= inv_s32;
            float nn0 = sqrtf(a0*a0 + 1e-10f), nn1 = sqrtf(a1*a1 + 1e-10f);
            float y0 = (1.0f / (1.0f + __expf(-nn0))) / nn0 * a0;
            float y1 = (1.0f / (1.0f + __expf(-nn1))) / nn1 * a1;
            if (pass == 0)      { qs0[lane] = y0; qs1[lane] = y1; }
            else if (pass == 1) { kp0[lane] = __float2half_rn(y0); kp1[lane] = __float2half_rn(y1); }
            else                { vp0[lane] = y0; vp1[lane] = y1; }
        }
        // l=1: lanes 0..15, output j = lane
        if (lane < 16) {
            float r0[3], r1[3];
            #pragma unroll
            for (int m = 0; m < 3; ++m) { r0[m] = 0.f; r1[m] = 0.f; }
            #pragma unroll
            for (int i = 0; i < 16; ++i) {
                float w = __ldg(&W1[i * 16 + lane]);
                #pragma unroll
                for (int m = 0; m < 3; ++m) {
                    r0[m] += xs0[32 + i*3 + m] * w;
                    r1[m] += xs1[32 + i*3 + m] * w;
                }
            }
            float ss0 = 0.f, ss1 = 0.f;
            #pragma unroll
            for (int m = 0; m < 3; ++m) {
                r0[m] *= inv_s16; r1[m] *= inv_s16;
                ss0 += r0[m]*r0[m]; ss1 += r1[m]*r1[m];
            }
            float nn0 = sqrtf(ss0 + 1e-10f), nn1 = sqrtf(ss1 + 1e-10f);
            float sc0 = (1.0f / (1.0f + __expf(-nn0))) / nn0;
            float sc1 = (1.0f / (1.0f + __expf(-nn1))) / nn1;
            #pragma unroll
            for (int m = 0; m < 3; ++m) {
                int f = 32 + lane*3 + m;
                float y0 = sc0 * r0[m], y1 = sc1 * r1[m];
                if (pass == 0)      { qs0[f] = y0; qs1[f] = y1; }
                else if (pass == 1) { kp0[f] = __float2half_rn(y0); kp1[f] = __float2half_rn(y1); }
                else                { vp0[f] = y0; vp1[f] = y1; }
            }
        }
        // l=2: lanes 16..23, output j = lane-16
        else if (lane < 24) {
            const int j = lane - 16;
            float r0[5], r1[5];
            #pragma unroll
            for (int m = 0; m < 5; ++m) { r0[m] = 0.f; r1[m] = 0.f; }
            #pragma unroll
            for (int i = 0; i < 8; ++i) {
                float w = __ldg(&W2[i * 8 + j]);
                #pragma unroll
                for (int m = 0; m < 5; ++m) {
                    r0[m] += xs0[80 + i*5 + m] * w;
                    r1[m] += xs1[80 + i*5 + m] * w;
                }
            }
            float ss0 = 0.f, ss1 = 0.f;
            #pragma unroll
            for (int m = 0; m < 5; ++m) {
                r0[m] *= inv_s8; r1[m] *= inv_s8;
                ss0 += r0[m]*r0[m]; ss1 += r1[m]*r1[m];
            }
            float nn0 = sqrtf(ss0 + 1e-10f), nn1 = sqrtf(ss1 + 1e-10f);
            float sc0 = (1.0f / (1.0f + __expf(-nn0))) / nn0;
            float sc1 = (1.0f / (1.0f + __expf(-nn1))) / nn1;
            #pragma unroll
            for (int m = 0; m < 5; ++m) {
                int f = 80 + j*5 + m;
                float y0 = sc0 * r0[m], y1 = sc1 * r1[m];
                if (pass == 0)      { qs0[f] = y0; qs1[f] = y1; }
                else if (pass == 1) { kp0[f] = __float2half_rn(y0); kp1[f] = __float2half_rn(y1); }
                else                { vp0[f] = y0; vp1[f] = y1; }
            }
        }
        __syncwarp();
    }

    // ---- Wd contraction: qW[n][f][4], both nodes share every Wd wavefront ----
    const float c0 = 0.02176061898f;     // 1/sqrt(2112)
    const float c1 = c0 * 0.5773502692f; // c0/sqrt(3)
    const float c2 = c0 * 0.4472135955f; // c0/sqrt(5)
    const float4* D0 = reinterpret_cast<const float4*>(Wd0);
    const float4* D1 = reinterpret_cast<const float4*>(Wd1);
    const float4* D2 = reinterpret_cast<const float4*>(Wd2);

    // l=0: j = lane
    {
        float4 A0 = make_float4(0.f,0.f,0.f,0.f);
        float4 A1 = make_float4(0.f,0.f,0.f,0.f);
        #pragma unroll
        for (int i = 0; i < 32; ++i) {
            float4 w = __ldg(&D0[i * 32 + lane]);
            float q0 = qs0[i], q1 = qs1[i];
            A0.x += q0*w.x; A0.y += q0*w.y; A0.z += q0*w.z; A0.w += q0*w.w;
            A1.x += q1*w.x; A1.y += q1*w.y; A1.z += q1*w.z; A1.w += q1*w.w;
        }
        store_qw(n0, lane, A0, c0);
        store_qw(n1, lane, A1, c0);
    }
    // l=1: lanes 0..15, j = lane
    if (lane < 16) {
        float4 B0[3], B1[3];
        #pragma unroll
        for (int m = 0; m < 3; ++m) {
            B0[m] = make_float4(0.f,0.f,0.f,0.f);
            B1[m] = make_float4(0.f,0.f,0.f,0.f);
        }
        #pragma unroll
        for (int i = 0; i < 16; ++i) {
            float4 w = __ldg(&D1[i * 16 + lane]);
            #pragma unroll
            for (int m = 0; m < 3; ++m) {
                float q0 = qs0[32 + i*3 + m], q1 = qs1[32 + i*3 + m];
                B0[m].x += q0*w.x; B0[m].y += q0*w.y; B0[m].z += q0*w.z; B0[m].w += q0*w.w;
                B1[m].x += q1*w.x; B1[m].y += q1*w.y; B1[m].z += q1*w.z; B1[m].w += q1*w.w;
            }
        }
        #pragma unroll
        for (int m = 0; m < 3; ++m) {
            int f = 32 + lane*3 + m;
            store_qw(n0, f, B0[m], c1);
            store_qw(n1, f, B1[m], c1);
        }
    }
    // l=2: lanes 16..23, j = lane-16
    else if (lane < 24) {
        const int j = lane - 16;
        float4 C0[5], C1[5];
        #pragma unroll
        for (int m = 0; m < 5; ++m) {
            C0[m] = make_float4(0.f,0.f,0.f,0.f);
            C1[m] = make_float4(0.f,0.f,0.f,0.f);
        }
        #pragma unroll
        for (int i = 0; i < 8; ++i) {
            float4 w = __ldg(&D2[i * 8 + j]);
            #pragma unroll
            for (int m = 0; m < 5; ++m) {
                float q0 = qs0[80 + i*5 + m], q1 = qs1[80 + i*5 + m];
                C0[m].x += q0*w.x; C0[m].y += q0*w.y; C0[m].z += q0*w.z; C0[m].w += q0*w.w;
                C1[m].x += q1*w.x; C1[m].y += q1*w.y; C1[m].z += q1*w.z; C1[m].w += q1*w.w;
            }
        }
        #pragma unroll
        for (int m = 0; m < 5; ++m) {
            int f = 80 + j*5 + m;
            store_qw(n0, f, C0[m], c2);
            store_qw(n1, f, C1[m], c2);
        }
    }
}

// ---------------------------------------------------------------------------
// Binning kernels (CSR: src list sorted by dst)
// ---------------------------------------------------------------------------
__global__ void zero_cnt_kernel() {
    int i = blockIdx.x * blockDim.x + threadIdx.x;
    if (i < NNODES) g_cnt[i] = 0;
}

__global__ void hist_kernel(const int* __restrict__ dsts) {
    int e = blockIdx.x * blockDim.x + threadIdx.x;
    if (e < NEDGES) atomicAdd(&g_cnt[dsts[e]], 1);
}

// Single-block exclusive scan over g_cnt -> g_off, g_cur. 1024 threads.
__global__ __launch_bounds__(1024) void scan_kernel() {
    __shared__ int sp[1024];
    const int t = threadIdx.x;
    const int CH = (NNODES + 1023) / 1024;          // 49
    const int beg = t * CH;
    const int end = (beg + CH < NNODES) ? beg + CH : NNODES;

    int sum = 0;
    for (int i = beg; i < end; ++i) sum += g_cnt[i];
    sp[t] = sum;
    __syncthreads();
    for (int d = 1; d < 1024; d <<= 1) {
        int v = (t >= d) ? sp[t - d] : 0;
        __syncthreads();
        sp[t] += v;
        __syncthreads();
    }
    int run = (t > 0) ? sp[t - 1] : 0;
    for (int i = beg; i < end; ++i) {
        g_off[i] = run;
        g_cur[i] = run;
        run += g_cnt[i];
    }
    if (end == NNODES && beg < NNODES) g_off[NNODES] = run;
}

__global__ void scatter_kernel(const int* __restrict__ dsts, const int* __restrict__ srcs) {
    int e = blockIdx.x * blockDim.x + threadIdx.x;
    if (e < NEDGES) {
        int p = atomicAdd(&g_cur[dsts[e]], 1);
        g_ssrc[p] = srcs[e];
    }
}

// ---------------------------------------------------------------------------
// Edge kernel: ONE BLOCK (8 warps) PER DST NODE. No atomics anywhere.
// Warp w handles edges beg+w, beg+w+8, ... (parallel across the node's edges).
// qW[n] loaded once per warp (L1 hit after first), z + weighted-v accumulated
// in registers, combined via smem, out written once (finalize fused).
// ---------------------------------------------------------------------------
__global__ __launch_bounds__(256) void edge_kernel(float* __restrict__ out)
{
    __shared__ float sacc[8][FEAT];
    __shared__ float sz[8];

    const int n    = blockIdx.x;
    const int warp = threadIdx.x >> 5;
    const int lane = threadIdx.x & 31;
    const bool hasB = (lane < 28);
    const bool hasV = (lane < 30);

    const int beg = g_off[n];
    const int end = g_off[n + 1];

    // Preload + unpack qW[n] once per warp (same row -> L1 broadcast)
    const uint4* qw4 = reinterpret_cast<const uint4*>(g_qWh + (size_t)n * FEAT * 2);
    uint4 qa = qw4[lane];
    uint4 qb = hasB ? qw4[32 + lane] : make_uint4(0u, 0u, 0u, 0u);
    float2 a01f0 = __half22float2(*reinterpret_cast<__half2*>(&qa.x));
    float2 a23f0 = __half22float2(*reinterpret_cast<__half2*>(&qa.y));
    float2 a01f1 = __half22float2(*reinterpret_cast<__half2*>(&qa.z));
    float2 a23f1 = __half22float2(*reinterpret_cast<__half2*>(&qa.w));
    float2 b01f0 = __half22float2(*reinterpret_cast<__half2*>(&qb.x));
    float2 b23f0 = __half22float2(*reinterpret_cast<__half2*>(&qb.y));
    float2 b01f1 = __half22float2(*reinterpret_cast<__half2*>(&qb.z));
    float2 b23f1 = __half22float2(*reinterpret_cast<__half2*>(&qb.w));

    float z = 0.0f;
    float4 acc = make_float4(0.f, 0.f, 0.f, 0.f);

    for (int e = beg + warp; e < end; e += 8) {
        const int s = g_ssrc[e];
        const __half2* kr = reinterpret_cast<const __half2*>(g_kh + (size_t)s * FEAT);
        float2 kA = __half22float2(kr[lane]);
        float2 kB = make_float2(0.f, 0.f);
        if (hasB) kB = __half22float2(kr[32 + lane]);

        float ax = kA.x*a01f0.x + kA.y*a01f1.x + kB.x*b01f0.x + kB.y*b01f1.x;
        float ay = kA.x*a01f0.y + kA.y*a01f1.y + kB.x*b01f0.y + kB.y*b01f1.y;
        float az = kA.x*a23f0.x + kA.y*a23f1.x + kB.x*b23f0.x + kB.y*b23f1.x;
        float aw = kA.x*a23f0.y + kA.y*a23f1.y + kB.x*b23f0.y + kB.y*b23f1.y;
        #pragma unroll
        for (int off = 16; off > 0; off >>= 1) {
            ax += __shfl_xor_sync(0xffffffffu, ax, off);
            ay += __shfl_xor_sync(0xffffffffu, ay, off);
            az += __shfl_xor_sync(0xffffffffu, az, off);
            aw += __shfl_xor_sync(0xffffffffu, aw, off);
        }
        const float ev = 0.25f * (__expf(ax) + __expf(ay) + __expf(az) + __expf(aw));
        z += ev;
        const float w = sqrtf(ev);
        if (hasV) {
            float4 v4 = reinterpret_cast<const float4*>(g_v + (size_t)s * FEAT)[lane];
            acc.x += w * v4.x; acc.y += w * v4.y;
            acc.z += w * v4.z; acc.w += w * v4.w;
        }
    }

    // Combine the 8 warps' partials
    if (hasV) *reinterpret_cast<float4*>(&sacc[warp][lane * 4]) = acc;
    if (lane == 0) sz[warp] = z;
    __syncthreads();

    const int t = threadIdx.x;
    if (t < FEAT) {
        float s_ = 0.0f, zz = 0.0f;
        #pragma unroll
        for (int wi = 0; wi < 8; ++wi) { s_ += sacc[wi][t]; zz += sz[wi]; }
        const float sc = (zz > 0.0f) ? rsqrtf(zz) : 0.0f;
        out[(size_t)n * FEAT + t] = g_v[(size_t)n * FEAT + t] + s_ * sc;
    }
}

// ---------------------------------------------------------------------------
extern "C" void kernel_launch(void* const* d_in, const int* in_sizes, int n_in,
                              void* d_out, int out_size)
{
    const float* x   = (const float*)d_in[0];
    const float* Wq0 = (const float*)d_in[1];
    const float* Wq1 = (const float*)d_in[2];
    const float* Wq2 = (const float*)d_in[3];
    const float* Wk0 = (const float*)d_in[4];
    const float* Wk1 = (const float*)d_in[5];
    const float* Wk2 = (const float*)d_in[6];
    const float* Wv0 = (const float*)d_in[7];
    const float* Wv1 = (const float*)d_in[8];
    const float* Wv2 = (const float*)d_in[9];
    const float* Wd0 = (const float*)d_in[10];
    const float* Wd1 = (const float*)d_in[11];
    const float* Wd2 = (const float*)d_in[12];
    const int* edge_dst = (const int*)d_in[13];
    const int* edge_src = (const int*)d_in[14];
    float* out = (float*)d_out;

    // CSR binning
    zero_cnt_kernel<<<(NNODES + 255) / 256, 256>>>();
    hist_kernel<<<(NEDGES + 255) / 256, 256>>>(edge_dst);
    scan_kernel<<<1, 1024>>>();
    scatter_kernel<<<(NEDGES + 255) / 256, 256>>>(edge_dst, edge_src);

    // Node kernel: 16 nodes/block (2 per warp), 50000/16 = 3125 blocks
    node_kernel<<<NNODES / 16, 256>>>(x, Wq0, Wq1, Wq2, Wk0, Wk1, Wk2,
                                      Wv0, Wv1, Wv2, Wd0, Wd1, Wd2);

    // Edge kernel: one block per dst node, no atomics
    edge_kernel<<<NNODES, 256>>>(out);
}

// round 10
// speedup vs baseline: 1.2177x; 1.1302x over previous
#include <cuda_runtime.h>
#include <cuda_fp16.h>
#include <math.h>

#define NNODES 50000
#define NEDGES 800000
#define FEAT   120
#define FPAD   128   // padded feature count for qW / k rows

// Scratch (static __device__ arrays — allocation-free per harness rules)
__device__ uint2  g_qW2[(size_t)NNODES * FPAD];  // [n][128 feats][4 heads fp16] = 1024B/row, 51.2 MB
__device__ __half g_kh [(size_t)NNODES * FPAD];  // [n][128] fp16, 12.8 MB
__device__ float  g_v  [(size_t)NNODES * FEAT];  // 24 MB
__device__ float  g_z  [NNODES];

__device__ __forceinline__ void store_qw(int n, int f, float4 a, float c) {
    __half2 h01 = __floats2half2_rn(a.x * c, a.y * c);
    __half2 h23 = __floats2half2_rn(a.z * c, a.w * c);
    uint2 u;
    u.x = *reinterpret_cast<unsigned*>(&h01);
    u.y = *reinterpret_cast<unsigned*>(&h23);
    g_qW2[(size_t)n * FPAD + f] = u;
}

// ---------------------------------------------------------------------------
// Node kernel (R4 structure): one warp per 2 nodes, 8 warps per block.
// 50000 = 16 * 3125 exactly -> no bounds checks.
// Writes padded feature rows (features 120..127 zeroed) for qW and k.
// ---------------------------------------------------------------------------
__global__ __launch_bounds__(256) void node_kernel(
    const float* __restrict__ x,
    const float* __restrict__ Wq0, const float* __restrict__ Wq1, const float* __restrict__ Wq2,
    const float* __restrict__ Wk0, const float* __restrict__ Wk1, const float* __restrict__ Wk2,
    const float* __restrict__ Wv0, const float* __restrict__ Wv1, const float* __restrict__ Wv2,
    const float* __restrict__ Wd0, const float* __restrict__ Wd1, const float* __restrict__ Wd2,
    float* __restrict__ out)
{
    __shared__ float sX[8][2][FEAT];
    __shared__ float sQ[8][2][FEAT];

    const int warp = threadIdx.x >> 5;
    const int lane = threadIdx.x & 31;
    const int n0 = blockIdx.x * 16 + warp * 2;
    const int n1 = n0 + 1;

    float* xs0 = sX[warp][0];
    float* xs1 = sX[warp][1];
    float* qs0 = sQ[warp][0];
    float* qs1 = sQ[warp][1];

    for (int f = lane; f < FEAT; f += 32) {
        xs0[f] = x[(size_t)n0 * FEAT + f];
        xs1[f] = x[(size_t)n1 * FEAT + f];
        out[(size_t)n0 * FEAT + f] = 0.0f;   // out accumulates edge sums
        out[(size_t)n1 * FEAT + f] = 0.0f;
    }
    if (lane == 0) { g_z[n0] = 0.0f; g_z[n1] = 0.0f; }
    if (lane >= 24) {                         // zero the pad features 120..127
        int f = 96 + lane;
        g_kh[(size_t)n0 * FPAD + f] = __float2half_rn(0.0f);
        g_kh[(size_t)n1 * FPAD + f] = __float2half_rn(0.0f);
        g_qW2[(size_t)n0 * FPAD + f] = make_uint2(0u, 0u);
        g_qW2[(size_t)n1 * FPAD + f] = make_uint2(0u, 0u);
    }
    __syncwarp();

    const float inv_s32 = 0.1767766953f;   // 1/sqrt(32)
    const float inv_s16 = 0.25f;
    const float inv_s8  = 0.3535533906f;   // 1/sqrt(8)

    __half* kp0 = g_kh + (size_t)n0 * FPAD;
    __half* kp1 = g_kh + (size_t)n1 * FPAD;
    float*  vp0 = g_v  + (size_t)n0 * FEAT;
    float*  vp1 = g_v  + (size_t)n1 * FEAT;

    #pragma unroll 1
    for (int pass = 0; pass < 3; ++pass) {
        const float* W0 = (pass == 0) ? Wq0 : ((pass == 1) ? Wk0 : Wv0);
        const float* W1 = (pass == 0) ? Wq1 : ((pass == 1) ? Wk1 : Wv1);
        const float* W2 = (pass == 0) ? Wq2 : ((pass == 1) ? Wk2 : Wv2);

        // l=0: output j = lane
        {
            float a0 = 0.f, a1 = 0.f;
            #pragma unroll
            for (int i = 0; i < 32; ++i) {
                float w = __ldg(&W0[i * 32 + lane]);
                a0 += xs0[i] * w;
                a1 += xs1[i] * w;
            }
            a0 *= inv_s32; a1 *= inv_s32;
            float nn0 = sqrtf(a0*a0 + 1e-10f), nn1 = sqrtf(a1*a1 + 1e-10f);
            float y0 = (1.0f / (1.0f + __expf(-nn0))) / nn0 * a0;
            float y1 = (1.0f / (1.0f + __expf(-nn1))) / nn1 * a1;
            if (pass == 0)      { qs0[lane] = y0; qs1[lane] = y1; }
            else if (pass == 1) { kp0[lane] = __float2half_rn(y0); kp1[lane] = __float2half_rn(y1); }
            else                { vp0[lane] = y0; vp1[lane] = y1; }
        }
        // l=1: lanes 0..15, output j = lane
        if (lane < 16) {
            float r0[3], r1[3];
            #pragma unroll
            for (int m = 0; m < 3; ++m) { r0[m] = 0.f; r1[m] = 0.f; }
            #pragma unroll
            for (int i = 0; i < 16; ++i) {
                float w = __ldg(&W1[i * 16 + lane]);
                #pragma unroll
                for (int m = 0; m < 3; ++m) {
                    r0[m] += xs0[32 + i*3 + m] * w;
                    r1[m] += xs1[32 + i*3 + m] * w;
                }
            }
            float ss0 = 0.f, ss1 = 0.f;
            #pragma unroll
            for (int m = 0; m < 3; ++m) {
                r0[m] *= inv_s16; r1[m] *= inv_s16;
                ss0 += r0[m]*r0[m]; ss1 += r1[m]*r1[m];
            }
            float nn0 = sqrtf(ss0 + 1e-10f), nn1 = sqrtf(ss1 + 1e-10f);
            float sc0 = (1.0f / (1.0f + __expf(-nn0))) / nn0;
            float sc1 = (1.0f / (1.0f + __expf(-nn1))) / nn1;
            #pragma unroll
            for (int m = 0; m < 3; ++m) {
                int f = 32 + lane*3 + m;
                float y0 = sc0 * r0[m], y1 = sc1 * r1[m];
                if (pass == 0)      { qs0[f] = y0; qs1[f] = y1; }
                else if (pass == 1) { kp0[f] = __float2half_rn(y0); kp1[f] = __float2half_rn(y1); }
                else                { vp0[f] = y0; vp1[f] = y1; }
            }
        }
        // l=2: lanes 16..23, output j = lane-16
        else if (lane < 24) {
            const int j = lane - 16;
            float r0[5], r1[5];
            #pragma unroll
            for (int m = 0; m < 5; ++m) { r0[m] = 0.f; r1[m] = 0.f; }
            #pragma unroll
            for (int i = 0; i < 8; ++i) {
                float w = __ldg(&W2[i * 8 + j]);
                #pragma unroll
                for (int m = 0; m < 5; ++m) {
                    r0[m] += xs0[80 + i*5 + m] * w;
                    r1[m] += xs1[80 + i*5 + m] * w;
                }
            }
            float ss0 = 0.f, ss1 = 0.f;
            #pragma unroll
            for (int m = 0; m < 5; ++m) {
                r0[m] *= inv_s8; r1[m] *= inv_s8;
                ss0 += r0[m]*r0[m]; ss1 += r1[m]*r1[m];
            }
            float nn0 = sqrtf(ss0 + 1e-10f), nn1 = sqrtf(ss1 + 1e-10f);
            float sc0 = (1.0f / (1.0f + __expf(-nn0))) / nn0;
            float sc1 = (1.0f / (1.0f + __expf(-nn1))) / nn1;
            #pragma unroll
            for (int m = 0; m < 5; ++m) {
                int f = 80 + j*5 + m;
                float y0 = sc0 * r0[m], y1 = sc1 * r1[m];
                if (pass == 0)      { qs0[f] = y0; qs1[f] = y1; }
                else if (pass == 1) { kp0[f] = __float2half_rn(y0); kp1[f] = __float2half_rn(y1); }
                else                { vp0[f] = y0; vp1[f] = y1; }
            }
        }
        __syncwarp();
    }

    // ---- Wd contraction: qW[n][f][4], both nodes share every Wd wavefront ----
    const float c0 = 0.02176061898f;     // 1/sqrt(2112)
    const float c1 = c0 * 0.5773502692f; // c0/sqrt(3)
    const float c2 = c0 * 0.4472135955f; // c0/sqrt(5)
    const float4* D0 = reinterpret_cast<const float4*>(Wd0);
    const float4* D1 = reinterpret_cast<const float4*>(Wd1);
    const float4* D2 = reinterpret_cast<const float4*>(Wd2);

    // l=0: j = lane
    {
        float4 A0 = make_float4(0.f,0.f,0.f,0.f);
        float4 A1 = make_float4(0.f,0.f,0.f,0.f);
        #pragma unroll
        for (int i = 0; i < 32; ++i) {
            float4 w = __ldg(&D0[i * 32 + lane]);
            float q0 = qs0[i], q1 = qs1[i];
            A0.x += q0*w.x; A0.y += q0*w.y; A0.z += q0*w.z; A0.w += q0*w.w;
            A1.x += q1*w.x; A1.y += q1*w.y; A1.z += q1*w.z; A1.w += q1*w.w;
        }
        store_qw(n0, lane, A0, c0);
        store_qw(n1, lane, A1, c0);
    }
    // l=1: lanes 0..15, j = lane
    if (lane < 16) {
        float4 B0[3], B1[3];
        #pragma unroll
        for (int m = 0; m < 3; ++m) {
            B0[m] = make_float4(0.f,0.f,0.f,0.f);
            B1[m] = make_float4(0.f,0.f,0.f,0.f);
        }
        #pragma unroll
        for (int i = 0; i < 16; ++i) {
            float4 w = __ldg(&D1[i * 16 + lane]);
            #pragma unroll
            for (int m = 0; m < 3; ++m) {
                float q0 = qs0[32 + i*3 + m], q1 = qs1[32 + i*3 + m];
                B0[m].x += q0*w.x; B0[m].y += q0*w.y; B0[m].z += q0*w.z; B0[m].w += q0*w.w;
                B1[m].x += q1*w.x; B1[m].y += q1*w.y; B1[m].z += q1*w.z; B1[m].w += q1*w.w;
            }
        }
        #pragma unroll
        for (int m = 0; m < 3; ++m) {
            int f = 32 + lane*3 + m;
            store_qw(n0, f, B0[m], c1);
            store_qw(n1, f, B1[m], c1);
        }
    }
    // l=2: lanes 16..23, j = lane-16
    else if (lane < 24) {
        const int j = lane - 16;
        float4 C0[5], C1[5];
        #pragma unroll
        for (int m = 0; m < 5; ++m) {
            C0[m] = make_float4(0.f,0.f,0.f,0.f);
            C1[m] = make_float4(0.f,0.f,0.f,0.f);
        }
        #pragma unroll
        for (int i = 0; i < 8; ++i) {
            float4 w = __ldg(&D2[i * 8 + j]);
            #pragma unroll
            for (int m = 0; m < 5; ++m) {
                float q0 = qs0[80 + i*5 + m], q1 = qs1[80 + i*5 + m];
                C0[m].x += q0*w.x; C0[m].y += q0*w.y; C0[m].z += q0*w.z; C0[m].w += q0*w.w;
                C1[m].x += q1*w.x; C1[m].y += q1*w.y; C1[m].z += q1*w.z; C1[m].w += q1*w.w;
            }
        }
        #pragma unroll
        for (int m = 0; m < 5; ++m) {
            int f = 80 + j*5 + m;
            store_qw(n0, f, C0[m], c2);
            store_qw(n1, f, C1[m], c2);
        }
    }
}

// ---------------------------------------------------------------------------
// Fused edge kernel: FOUR edges per warp, 8 lanes per edge.
// Lane u of group g owns features 16u..16u+15 of edge (warp_e_base + g).
// ev = mean_h exp(qW[dst]·k[src]); z[dst] += ev (1 instr/warp);
// out[dst] += sqrt(ev)*v[src] via each group's 30 float4 chunks.
// 800000 = 25000 blocks * 8 warps * 4 edges exactly.
// ---------------------------------------------------------------------------
__global__ __launch_bounds__(256) void edge_kernel(
    const int* __restrict__ dsts, const int* __restrict__ srcs,
    float* __restrict__ out)
{
    const int warp = threadIdx.x >> 5;
    const int lane = threadIdx.x & 31;
    const int g = lane >> 3;       // edge slot within warp (0..3)
    const int u = lane & 7;        // sublane within edge group
    const int e = (blockIdx.x * 8 + warp) * 4 + g;

    const int d = dsts[e];
    const int s = srcs[e];

    const uint4* qrow = reinterpret_cast<const uint4*>(g_qW2 + (size_t)d * FPAD) + u * 8;
    const uint4* krow = reinterpret_cast<const uint4*>(g_kh  + (size_t)s * FPAD) + u * 2;

    // k features 16u..16u+15 as 8 float2 pairs
    uint4 k0 = krow[0];
    uint4 k1 = krow[1];
    float2 kf[8];
    kf[0] = __half22float2(*reinterpret_cast<__half2*>(&k0.x));
    kf[1] = __half22float2(*reinterpret_cast<__half2*>(&k0.y));
    kf[2] = __half22float2(*reinterpret_cast<__half2*>(&k0.z));
    kf[3] = __half22float2(*reinterpret_cast<__half2*>(&k0.w));
    kf[4] = __half22float2(*reinterpret_cast<__half2*>(&k1.x));
    kf[5] = __half22float2(*reinterpret_cast<__half2*>(&k1.y));
    kf[6] = __half22float2(*reinterpret_cast<__half2*>(&k1.z));
    kf[7] = __half22float2(*reinterpret_cast<__half2*>(&k1.w));

    float ax = 0.f, ay = 0.f, az = 0.f, aw = 0.f;
    #pragma unroll
    for (int i = 0; i < 8; ++i) {
        uint4 q = qrow[i];      // features f0=16u+2i (x,y = h01,h23) and f1=f0+1 (z,w)
        float2 h01a = __half22float2(*reinterpret_cast<__half2*>(&q.x));
        float2 h23a = __half22float2(*reinterpret_cast<__half2*>(&q.y));
        float2 h01b = __half22float2(*reinterpret_cast<__half2*>(&q.z));
        float2 h23b = __half22float2(*reinterpret_cast<__half2*>(&q.w));
        float kx = kf[i].x, ky = kf[i].y;
        ax += h01a.x*kx + h01b.x*ky;
        ay += h01a.y*kx + h01b.y*ky;
        az += h23a.x*kx + h23b.x*ky;
        aw += h23a.y*kx + h23b.y*ky;
    }
    // reduce within the 8-lane group (offsets stay inside the group)
    #pragma unroll
    for (int off = 4; off > 0; off >>= 1) {
        ax += __shfl_xor_sync(0xffffffffu, ax, off);
        ay += __shfl_xor_sync(0xffffffffu, ay, off);
        az += __shfl_xor_sync(0xffffffffu, az, off);
        aw += __shfl_xor_sync(0xffffffffu, aw, off);
    }

    const float ev = 0.25f * (__expf(ax) + __expf(ay) + __expf(az) + __expf(aw));
    if (u == 0) atomicAdd(&g_z[d], ev);   // 4 lanes active -> one ATOMG instr/warp
    const float w = sqrtf(ev);

    // v accumulation: each group handles its own edge's 30 float4 chunks
    const float4* vrow = reinterpret_cast<const float4*>(g_v + (size_t)s * FEAT);
    float* orow = out + (size_t)d * FEAT;
    #pragma unroll
    for (int c = u; c < FEAT / 4; c += 8) {   // u<6: 4 chunks, u>=6: 3 chunks
        float4 v4 = vrow[c];
        float* p = orow + c * 4;
        asm volatile("red.global.add.v4.f32 [%0], {%1, %2, %3, %4};"
                     :: "l"(p), "f"(w * v4.x), "f"(w * v4.y), "f"(w * v4.z), "f"(w * v4.w)
                     : "memory");
    }
}

// ---------------------------------------------------------------------------
// Finalize: out = v_node + out * rsqrt(z)   (z==0 -> no edges -> out sum is 0)
// ---------------------------------------------------------------------------
__global__ __launch_bounds__(256) void finalize_kernel(float* __restrict__ out)
{
    const int t = blockIdx.x * blockDim.x + threadIdx.x;
    if (t >= NNODES * (FEAT / 4)) return;
    const int n = t / (FEAT / 4);
    const float zz = g_z[n];
    const float sc = (zz > 0.0f) ? rsqrtf(zz) : 0.0f;
    float4 o = reinterpret_cast<float4*>(out)[t];
    float4 v = reinterpret_cast<const float4*>(g_v)[t];
    o.x = v.x + o.x * sc;
    o.y = v.y + o.y * sc;
    o.z = v.z + o.z * sc;
    o.w = v.w + o.w * sc;
    reinterpret_cast<float4*>(out)[t] = o;
}

// ---------------------------------------------------------------------------
extern "C" void kernel_launch(void* const* d_in, const int* in_sizes, int n_in,
                              void* d_out, int out_size)
{
    const float* x   = (const float*)d_in[0];
    const float* Wq0 = (const float*)d_in[1];
    const float* Wq1 = (const float*)d_in[2];
    const float* Wq2 = (const float*)d_in[3];
    const float* Wk0 = (const float*)d_in[4];
    const float* Wk1 = (const float*)d_in[5];
    const float* Wk2 = (const float*)d_in[6];
    const float* Wv0 = (const float*)d_in[7];
    const float* Wv1 = (const float*)d_in[8];
    const float* Wv2 = (const float*)d_in[9];
    const float* Wd0 = (const float*)d_in[10];
    const float* Wd1 = (const float*)d_in[11];
    const float* Wd2 = (const float*)d_in[12];
    const int* edge_dst = (const int*)d_in[13];
    const int* edge_src = (const int*)d_in[14];
    float* out = (float*)d_out;

    // Node kernel: 16 nodes/block (2 per warp), 50000/16 = 3125 blocks
    node_kernel<<<NNODES / 16, 256>>>(x, Wq0, Wq1, Wq2, Wk0, Wk1, Wk2,
                                      Wv0, Wv1, Wv2, Wd0, Wd1, Wd2, out);

    // Fused edge kernel: 32 edges/block (4 per warp), 800000/32 = 25000 blocks
    edge_kernel<<<NEDGES / 32, 256>>>(edge_dst, edge_src, out);

    // Finalize: one thread per float4 of out
    const int nt = NNODES * (FEAT / 4);
    finalize_kernel<<<(nt + 255) / 256, 256>>>(out);
}

// round 11
// speedup vs baseline: 1.3407x; 1.1010x over previous
#include <cuda_runtime.h>
#include <cuda_fp16.h>
#include <math.h>

#define NNODES 50000
#define NEDGES 800000
#define FEAT   120

// Scratch (static __device__ arrays — allocation-free per harness rules)
__device__ __half2 g_qWh[(size_t)NNODES * FEAT * 2]; // [n][f][4 heads as 2x half2], 48 MB
__device__ __half  g_kh [(size_t)NNODES * FEAT];     // 12 MB
__device__ float   g_v  [(size_t)NNODES * FEAT];     // 24 MB
__device__ float   g_z  [NNODES];

__device__ __forceinline__ void store_qw(int n, int f, float4 a, float c) {
    __half2 h01 = __floats2half2_rn(a.x * c, a.y * c);
    __half2 h23 = __floats2half2_rn(a.z * c, a.w * c);
    uint2 u;
    u.x = *reinterpret_cast<unsigned*>(&h01);
    u.y = *reinterpret_cast<unsigned*>(&h23);
    reinterpret_cast<uint2*>(g_qWh)[(size_t)n * FEAT + f] = u;
}

// ---------------------------------------------------------------------------
// Node kernel: one warp per 2 nodes, 8 warps (16 nodes) per block.
// Node-paired smem layout [f][2]: one LDS.64 broadcast serves both nodes.
// 50000 = 16 * 3125 exactly -> no bounds checks.
// ---------------------------------------------------------------------------
__global__ __launch_bounds__(256, 4) void node_kernel(
    const float* __restrict__ x,
    const float* __restrict__ Wq0, const float* __restrict__ Wq1, const float* __restrict__ Wq2,
    const float* __restrict__ Wk0, const float* __restrict__ Wk1, const float* __restrict__ Wk2,
    const float* __restrict__ Wv0, const float* __restrict__ Wv1, const float* __restrict__ Wv2,
    const float* __restrict__ Wd0, const float* __restrict__ Wd1, const float* __restrict__ Wd2,
    float* __restrict__ out)
{
    __shared__ __align__(8) float sX[8][FEAT * 2];   // [warp][f*2 + node]
    __shared__ __align__(8) float sQ[8][FEAT * 2];

    const int warp = threadIdx.x >> 5;
    const int lane = threadIdx.x & 31;
    const int n0 = blockIdx.x * 16 + warp * 2;
    const int n1 = n0 + 1;

    float* xs = sX[warp];
    float* qs = sQ[warp];

    for (int f = lane; f < FEAT; f += 32) {
        float2 xv = make_float2(x[(size_t)n0 * FEAT + f], x[(size_t)n1 * FEAT + f]);
        *reinterpret_cast<float2*>(&xs[2 * f]) = xv;
        out[(size_t)n0 * FEAT + f] = 0.0f;   // out accumulates edge sums
        out[(size_t)n1 * FEAT + f] = 0.0f;
    }
    if (lane == 0) { g_z[n0] = 0.0f; g_z[n1] = 0.0f; }
    __syncwarp();

    const float inv_s32 = 0.1767766953f;   // 1/sqrt(32)
    const float inv_s16 = 0.25f;
    const float inv_s8  = 0.3535533906f;   // 1/sqrt(8)

    __half* kp0 = g_kh + (size_t)n0 * FEAT;
    __half* kp1 = g_kh + (size_t)n1 * FEAT;
    float*  vp0 = g_v  + (size_t)n0 * FEAT;
    float*  vp1 = g_v  + (size_t)n1 * FEAT;

    #pragma unroll 1
    for (int pass = 0; pass < 3; ++pass) {
        const float* W0 = (pass == 0) ? Wq0 : ((pass == 1) ? Wk0 : Wv0);
        const float* W1 = (pass == 0) ? Wq1 : ((pass == 1) ? Wk1 : Wv1);
        const float* W2 = (pass == 0) ? Wq2 : ((pass == 1) ? Wk2 : Wv2);

        // l=0: output j = lane
        {
            float a0 = 0.f, a1 = 0.f;
            #pragma unroll
            for (int i = 0; i < 32; ++i) {
                float2 xv = *reinterpret_cast<const float2*>(&xs[2 * i]);
                float w = __ldg(&W0[i * 32 + lane]);
                a0 += xv.x * w;
                a1 += xv.y * w;
            }
            a0 *= inv_s32; a1 *= inv_s32;
            float nn0 = sqrtf(a0*a0 + 1e-10f), nn1 = sqrtf(a1*a1 + 1e-10f);
            float y0 = (1.0f / (1.0f + __expf(-nn0))) / nn0 * a0;
            float y1 = (1.0f / (1.0f + __expf(-nn1))) / nn1 * a1;
            if (pass == 0)      *reinterpret_cast<float2*>(&qs[2 * lane]) = make_float2(y0, y1);
            else if (pass == 1) { kp0[lane] = __float2half_rn(y0); kp1[lane] = __float2half_rn(y1); }
            else                { vp0[lane] = y0; vp1[lane] = y1; }
        }
        // l=1: lanes 0..15, output j = lane
        if (lane < 16) {
            float r0[3], r1[3];
            #pragma unroll
            for (int m = 0; m < 3; ++m) { r0[m] = 0.f; r1[m] = 0.f; }
            #pragma unroll
            for (int i = 0; i < 16; ++i) {
                float w = __ldg(&W1[i * 16 + lane]);
                #pragma unroll
                for (int m = 0; m < 3; ++m) {
                    float2 xv = *reinterpret_cast<const float2*>(&xs[2 * (32 + i*3 + m)]);
                    r0[m] += xv.x * w;
                    r1[m] += xv.y * w;
                }
            }
            float ss0 = 0.f, ss1 = 0.f;
            #pragma unroll
            for (int m = 0; m < 3; ++m) {
                r0[m] *= inv_s16; r1[m] *= inv_s16;
                ss0 += r0[m]*r0[m]; ss1 += r1[m]*r1[m];
            }
            float nn0 = sqrtf(ss0 + 1e-10f), nn1 = sqrtf(ss1 + 1e-10f);
            float sc0 = (1.0f / (1.0f + __expf(-nn0))) / nn0;
            float sc1 = (1.0f / (1.0f + __expf(-nn1))) / nn1;
            #pragma unroll
            for (int m = 0; m < 3; ++m) {
                int f = 32 + lane*3 + m;
                float y0 = sc0 * r0[m], y1 = sc1 * r1[m];
                if (pass == 0)      *reinterpret_cast<float2*>(&qs[2 * f]) = make_float2(y0, y1);
                else if (pass == 1) { kp0[f] = __float2half_rn(y0); kp1[f] = __float2half_rn(y1); }
                else                { vp0[f] = y0; vp1[f] = y1; }
            }
        }
        // l=2: lanes 16..23, output j = lane-16
        else if (lane < 24) {
            const int j = lane - 16;
            float r0[5], r1[5];
            #pragma unroll
            for (int m = 0; m < 5; ++m) { r0[m] = 0.f; r1[m] = 0.f; }
            #pragma unroll
            for (int i = 0; i < 8; ++i) {
                float w = __ldg(&W2[i * 8 + j]);
                #pragma unroll
                for (int m = 0; m < 5; ++m) {
                    float2 xv = *reinterpret_cast<const float2*>(&xs[2 * (80 + i*5 + m)]);
                    r0[m] += xv.x * w;
                    r1[m] += xv.y * w;
                }
            }
            float ss0 = 0.f, ss1 = 0.f;
            #pragma unroll
            for (int m = 0; m < 5; ++m) {
                r0[m] *= inv_s8; r1[m] *= inv_s8;
                ss0 += r0[m]*r0[m]; ss1 += r1[m]*r1[m];
            }
            float nn0 = sqrtf(ss0 + 1e-10f), nn1 = sqrtf(ss1 + 1e-10f);
            float sc0 = (1.0f / (1.0f + __expf(-nn0))) / nn0;
            float sc1 = (1.0f / (1.0f + __expf(-nn1))) / nn1;
            #pragma unroll
            for (int m = 0; m < 5; ++m) {
                int f = 80 + j*5 + m;
                float y0 = sc0 * r0[m], y1 = sc1 * r1[m];
                if (pass == 0)      *reinterpret_cast<float2*>(&qs[2 * f]) = make_float2(y0, y1);
                else if (pass == 1) { kp0[f] = __float2half_rn(y0); kp1[f] = __float2half_rn(y1); }
                else                { vp0[f] = y0; vp1[f] = y1; }
            }
        }
        __syncwarp();
    }

    // ---- Wd contraction: qW[n][f][4]; paired q reads (one LDS.64 per i) ----
    const float c0 = 0.02176061898f;     // 1/sqrt(2112)
    const float c1 = c0 * 0.5773502692f; // c0/sqrt(3)
    const float c2 = c0 * 0.4472135955f; // c0/sqrt(5)
    const float4* D0 = reinterpret_cast<const float4*>(Wd0);
    const float4* D1 = reinterpret_cast<const float4*>(Wd1);
    const float4* D2 = reinterpret_cast<const float4*>(Wd2);

    // l=0: j = lane
    {
        float4 A0 = make_float4(0.f,0.f,0.f,0.f);
        float4 A1 = make_float4(0.f,0.f,0.f,0.f);
        #pragma unroll
        for (int i = 0; i < 32; ++i) {
            float4 w = __ldg(&D0[i * 32 + lane]);
            float2 qv = *reinterpret_cast<const float2*>(&qs[2 * i]);
            A0.x += qv.x*w.x; A0.y += qv.x*w.y; A0.z += qv.x*w.z; A0.w += qv.x*w.w;
            A1.x += qv.y*w.x; A1.y += qv.y*w.y; A1.z += qv.y*w.z; A1.w += qv.y*w.w;
        }
        store_qw(n0, lane, A0, c0);
        store_qw(n1, lane, A1, c0);
    }
    // l=1: lanes 0..15, j = lane
    if (lane < 16) {
        float4 B0[3], B1[3];
        #pragma unroll
        for (int m = 0; m < 3; ++m) {
            B0[m] = make_float4(0.f,0.f,0.f,0.f);
            B1[m] = make_float4(0.f,0.f,0.f,0.f);
        }
        #pragma unroll
        for (int i = 0; i < 16; ++i) {
            float4 w = __ldg(&D1[i * 16 + lane]);
            #pragma unroll
            for (int m = 0; m < 3; ++m) {
                float2 qv = *reinterpret_cast<const float2*>(&qs[2 * (32 + i*3 + m)]);
                B0[m].x += qv.x*w.x; B0[m].y += qv.x*w.y; B0[m].z += qv.x*w.z; B0[m].w += qv.x*w.w;
                B1[m].x += qv.y*w.x; B1[m].y += qv.y*w.y; B1[m].z += qv.y*w.z; B1[m].w += qv.y*w.w;
            }
        }
        #pragma unroll
        for (int m = 0; m < 3; ++m) {
            int f = 32 + lane*3 + m;
            store_qw(n0, f, B0[m], c1);
            store_qw(n1, f, B1[m], c1);
        }
    }
    // l=2: lanes 16..23, j = lane-16
    else if (lane < 24) {
        const int j = lane - 16;
        float4 C0[5], C1[5];
        #pragma unroll
        for (int m = 0; m < 5; ++m) {
            C0[m] = make_float4(0.f,0.f,0.f,0.f);
            C1[m] = make_float4(0.f,0.f,0.f,0.f);
        }
        #pragma unroll
        for (int i = 0; i < 8; ++i) {
            float4 w = __ldg(&D2[i * 8 + j]);
            #pragma unroll
            for (int m = 0; m < 5; ++m) {
                float2 qv = *reinterpret_cast<const float2*>(&qs[2 * (80 + i*5 + m)]);
                C0[m].x += qv.x*w.x; C0[m].y += qv.x*w.y; C0[m].z += qv.x*w.z; C0[m].w += qv.x*w.w;
                C1[m].x += qv.y*w.x; C1[m].y += qv.y*w.y; C1[m].z += qv.y*w.z; C1[m].w += qv.y*w.w;
            }
        }
        #pragma unroll
        for (int m = 0; m < 5; ++m) {
            int f = 80 + j*5 + m;
            store_qw(n0, f, C0[m], c2);
            store_qw(n1, f, C1[m], c2);
        }
    }
}

// ---------------------------------------------------------------------------
// Fused edge kernel (exact R4 shape): one warp per edge.
// ev = mean_h exp(qW[dst]·k[src]); z[dst] += ev; out[dst] += sqrt(ev)*v[src].
// ---------------------------------------------------------------------------
__global__ __launch_bounds__(256) void edge_kernel(
    const int* __restrict__ dsts, const int* __restrict__ srcs,
    float* __restrict__ out)
{
    const int e = (blockIdx.x * blockDim.x + threadIdx.x) >> 5;
    const int lane = threadIdx.x & 31;
    if (e >= NEDGES) return;
    const int d = dsts[e];
    const int s = srcs[e];

    const uint4*   qw4 = reinterpret_cast<const uint4*>(g_qWh + (size_t)d * FEAT * 2); // 60 entries
    const __half2* kr  = reinterpret_cast<const __half2*>(g_kh + (size_t)s * FEAT);    // 60 entries

    float ax = 0.f, ay = 0.f, az = 0.f, aw = 0.f;
    {
        uint4 q = qw4[lane];
        float2 kf = __half22float2(kr[lane]);
        float2 e0h01 = __half22float2(*reinterpret_cast<__half2*>(&q.x));
        float2 e0h23 = __half22float2(*reinterpret_cast<__half2*>(&q.y));
        float2 e1h01 = __half22float2(*reinterpret_cast<__half2*>(&q.z));
        float2 e1h23 = __half22float2(*reinterpret_cast<__half2*>(&q.w));
        ax += kf.x*e0h01.x + kf.y*e1h01.x; ay += kf.x*e0h01.y + kf.y*e1h01.y;
        az += kf.x*e0h23.x + kf.y*e1h23.x; aw += kf.x*e0h23.y + kf.y*e1h23.y;
    }
    if (lane < 28) {
        uint4 q = qw4[32 + lane];
        float2 kf = __half22float2(kr[32 + lane]);
        float2 e0h01 = __half22float2(*reinterpret_cast<__half2*>(&q.x));
        float2 e0h23 = __half22float2(*reinterpret_cast<__half2*>(&q.y));
        float2 e1h01 = __half22float2(*reinterpret_cast<__half2*>(&q.z));
        float2 e1h23 = __half22float2(*reinterpret_cast<__half2*>(&q.w));
        ax += kf.x*e0h01.x + kf.y*e1h01.x; ay += kf.x*e0h01.y + kf.y*e1h01.y;
        az += kf.x*e0h23.x + kf.y*e1h23.x; aw += kf.x*e0h23.y + kf.y*e1h23.y;
    }
    #pragma unroll
    for (int off = 16; off > 0; off >>= 1) {
        ax += __shfl_xor_sync(0xffffffffu, ax, off);
        ay += __shfl_xor_sync(0xffffffffu, ay, off);
        az += __shfl_xor_sync(0xffffffffu, az, off);
        aw += __shfl_xor_sync(0xffffffffu, aw, off);
    }
    const float ev = 0.25f * (__expf(ax) + __expf(ay) + __expf(az) + __expf(aw));
    if (lane == 0) atomicAdd(&g_z[d], ev);

    const float w = sqrtf(ev);
    if (lane < FEAT / 4) {  // 30 lanes, float4 chunk f = 4*lane
        float4 v4 = reinterpret_cast<const float4*>(g_v + (size_t)s * FEAT)[lane];
        float* p = out + (size_t)d * FEAT + lane * 4;
        asm volatile("red.global.add.v4.f32 [%0], {%1, %2, %3, %4};"
                     :: "l"(p), "f"(w * v4.x), "f"(w * v4.y), "f"(w * v4.z), "f"(w * v4.w)
                     : "memory");
    }
}

// ---------------------------------------------------------------------------
// Finalize: out = v_node + out * rsqrt(z)   (z==0 -> no edges -> out sum is 0)
// ---------------------------------------------------------------------------
__global__ __launch_bounds__(256) void finalize_kernel(float* __restrict__ out)
{
    const int t = blockIdx.x * blockDim.x + threadIdx.x;
    if (t >= NNODES * (FEAT / 4)) return;
    const int n = t / (FEAT / 4);
    const float zz = g_z[n];
    const float sc = (zz > 0.0f) ? rsqrtf(zz) : 0.0f;
    float4 o = reinterpret_cast<float4*>(out)[t];
    float4 v = reinterpret_cast<const float4*>(g_v)[t];
    o.x = v.x + o.x * sc;
    o.y = v.y + o.y * sc;
    o.z = v.z + o.z * sc;
    o.w = v.w + o.w * sc;
    reinterpret_cast<float4*>(out)[t] = o;
}

// ---------------------------------------------------------------------------
extern "C" void kernel_launch(void* const* d_in, const int* in_sizes, int n_in,
                              void* d_out, int out_size)
{
    const float* x   = (const float*)d_in[0];
    const float* Wq0 = (const float*)d_in[1];
    const float* Wq1 = (const float*)d_in[2];
    const float* Wq2 = (const float*)d_in[3];
    const float* Wk0 = (const float*)d_in[4];
    const float* Wk1 = (const float*)d_in[5];
    const float* Wk2 = (const float*)d_in[6];
    const float* Wv0 = (const float*)d_in[7];
    const float* Wv1 = (const float*)d_in[8];
    const float* Wv2 = (const float*)d_in[9];
    const float* Wd0 = (const float*)d_in[10];
    const float* Wd1 = (const float*)d_in[11];
    const float* Wd2 = (const float*)d_in[12];
    const int* edge_dst = (const int*)d_in[13];
    const int* edge_src = (const int*)d_in[14];
    float* out = (float*)d_out;

    // Node kernel: 16 nodes/block (2 per warp), 50000/16 = 3125 blocks
    node_kernel<<<NNODES / 16, 256>>>(x, Wq0, Wq1, Wq2, Wk0, Wk1, Wk2,
                                      Wv0, Wv1, Wv2, Wd0, Wd1, Wd2, out);

    // Fused edge kernel: 8 edges/block (one warp each)
    edge_kernel<<<(NEDGES + 7) / 8, 256>>>(edge_dst, edge_src, out);

    // Finalize: one thread per float4 of out
    const int nt = NNODES * (FEAT / 4);
    finalize_kernel<<<(nt + 255) / 256, 256>>>(out);
}